// round 2
// baseline (speedup 1.0000x reference)
#include <cuda_runtime.h>
#include <cuda_bf16.h>
#include <mma.h>
#include <cstdint>

using namespace nvcuda;

#define BATCH 32768
#define DIN   768
#define DHID  2048
#define TOPK  32

// -------- scratch (no cudaMalloc allowed) --------
__device__ float g_Wt[(size_t)DHID * DIN];       // W_dec transposed: [2048][768]
__device__ int   g_tidx[(size_t)BATCH * TOPK];
__device__ float g_tval[(size_t)BATCH * TOPK];

// ============================================================
// W_dec [768][2048] -> g_Wt [2048][768]
// ============================================================
__global__ void transpose_kernel(const float* __restrict__ W)
{
    __shared__ float tile[32][33];
    int bx = blockIdx.x * 32;  // h
    int by = blockIdx.y * 32;  // d
    int tx = threadIdx.x, ty = threadIdx.y;
#pragma unroll
    for (int i = 0; i < 32; i += 8)
        tile[ty + i][tx] = W[(size_t)(by + ty + i) * DHID + bx + tx];
    __syncthreads();
#pragma unroll
    for (int i = 0; i < 32; i += 8)
        g_Wt[(size_t)(bx + ty + i) * DIN + by + tx] = tile[tx][ty + i];
}

// ============================================================
// Encoder GEMM, 3xTF32: C[m,n] = sum_k A[m,k]*B[n,k] + bias[n]
// ============================================================
__global__ __launch_bounds__(256)
void gemm3xtf32(const float* __restrict__ A, const float* __restrict__ Bmat,
                const float* __restrict__ bias, float* __restrict__ C,
                int M, int N, int Kd)
{
    constexpr int BM = 128, BN = 128, BK = 16;
    __shared__ float As[BM][BK];
    __shared__ float Bs[BN][BK];
    __shared__ float BiasT[16][BN];

    int tid  = threadIdx.x;
    int warp = tid >> 5;
    int wm   = warp & 3;
    int wn   = warp >> 2;
    int m0 = blockIdx.y * BM;
    int n0 = blockIdx.x * BN;

    for (int i = tid; i < 16 * BN; i += 256)
        BiasT[i / BN][i % BN] = bias[n0 + (i % BN)];
    __syncthreads();

    using FragA = wmma::fragment<wmma::matrix_a, 16, 16, 8, wmma::precision::tf32, wmma::row_major>;
    using FragB = wmma::fragment<wmma::matrix_b, 16, 16, 8, wmma::precision::tf32, wmma::col_major>;
    using FragC = wmma::fragment<wmma::accumulator, 16, 16, 8, float>;

    FragC acc[2][4];
#pragma unroll
    for (int i = 0; i < 2; i++)
#pragma unroll
        for (int j = 0; j < 4; j++)
            wmma::load_matrix_sync(acc[i][j], &BiasT[0][wn * 64 + j * 16], BN, wmma::mem_row_major);
    __syncthreads();

    for (int kt = 0; kt < Kd; kt += BK) {
#pragma unroll
        for (int p = 0; p < 2; p++) {
            int idx = tid + p * 256;
            int r = idx >> 2, c4 = (idx & 3) * 4;
            *(float4*)&As[r][c4] = *(const float4*)&A[(size_t)(m0 + r) * Kd + kt + c4];
            *(float4*)&Bs[r][c4] = *(const float4*)&Bmat[(size_t)(n0 + r) * Kd + kt + c4];
        }
        __syncthreads();

#pragma unroll
        for (int ks = 0; ks < BK; ks += 8) {
            FragA ahi[2], alo[2];
#pragma unroll
            for (int i = 0; i < 2; i++) {
                wmma::load_matrix_sync(ahi[i], &As[wm * 32 + i * 16][ks], BK);
#pragma unroll
                for (int e = 0; e < ahi[i].num_elements; e++) {
                    float x = ahi[i].x[e];
                    float h = wmma::__float_to_tf32(x);
                    ahi[i].x[e] = h;
                    alo[i].x[e] = wmma::__float_to_tf32(x - h);
                }
            }
#pragma unroll
            for (int j = 0; j < 4; j++) {
                FragB bhi, blo;
                wmma::load_matrix_sync(bhi, &Bs[wn * 64 + j * 16][ks], BK);
#pragma unroll
                for (int e = 0; e < bhi.num_elements; e++) {
                    float x = bhi.x[e];
                    float h = wmma::__float_to_tf32(x);
                    bhi.x[e] = h;
                    blo.x[e] = wmma::__float_to_tf32(x - h);
                }
#pragma unroll
                for (int i = 0; i < 2; i++) {
                    wmma::mma_sync(acc[i][j], ahi[i], blo, acc[i][j]);
                    wmma::mma_sync(acc[i][j], alo[i], bhi, acc[i][j]);
                    wmma::mma_sync(acc[i][j], ahi[i], bhi, acc[i][j]);
                }
            }
        }
        __syncthreads();
    }

#pragma unroll
    for (int i = 0; i < 2; i++)
#pragma unroll
        for (int j = 0; j < 4; j++) {
            float* cp = &C[(size_t)(m0 + wm * 32 + i * 16) * N + n0 + wn * 64 + j * 16];
            wmma::store_matrix_sync(cp, acc[i][j], N, wmma::mem_row_major);
        }
}

// ============================================================
// Top-K with exact fp64 re-ranking of the ambiguous boundary.
// One warp per row, 2048 keys in 64 regs/lane.
// ============================================================
#define AMBIG_W 1e-4f
#define MAXCAND 16

__device__ __forceinline__ float key_decode(unsigned k)
{
    // inverse of monotone map
    return (k >= 0x80000000u) ? __uint_as_float(k ^ 0x80000000u)
                              : __uint_as_float(~k);
}

__global__ __launch_bounds__(256)
void topk_kernel(const float* __restrict__ hpre, float* __restrict__ hsp,
                 const float* __restrict__ x, const float* __restrict__ Wenc)
{
    int lane = threadIdx.x & 31;
    int warp = threadIdx.x >> 5;
    int row  = blockIdx.x * 8 + warp;
    const float* p = hpre + (size_t)row * DHID;

    __shared__ int    s_cidx[8][MAXCAND];
    __shared__ double s_cval[8][MAXCAND];
    __shared__ int    s_csel[8][MAXCAND];
    __shared__ unsigned s_chosen[8];

    unsigned key[64];
#pragma unroll
    for (int j = 0; j < 64; j++) {
        unsigned u = __float_as_uint(p[j * 32 + lane]);
        key[j] = (u & 0x80000000u) ? ~u : (u | 0x80000000u);
    }

    // binary search: largest T with count(key >= T) >= TOPK
    unsigned lo = 0u, hi = 0xFFFFFFFFu;
#pragma unroll 1
    for (int it = 0; it < 32; ++it) {
        if (lo >= hi) break;
        unsigned span = hi - lo;
        unsigned mid = lo + (span >> 1) + (span & 1u);
        int c = 0;
#pragma unroll
        for (int j = 0; j < 64; j++) c += (key[j] >= mid) ? 1 : 0;
        c = __reduce_add_sync(0xFFFFFFFFu, c);
        if (c >= TOPK) lo = mid; else hi = mid - 1;
    }
    unsigned T = lo;

    int cg = 0;
#pragma unroll
    for (int j = 0; j < 64; j++) cg += (key[j] > T) ? 1 : 0;
    cg = __reduce_add_sync(0xFFFFFFFFu, cg);
    int rem = TOPK - cg;   // #(==T) to take, ascending index

    unsigned lmask = (1u << lane) - 1u;
    unsigned long long selmask = 0ull;
    unsigned kmin_in = 0xFFFFFFFFu;   // min selected key
    unsigned kmax_out = 0u;           // max unselected key
#pragma unroll 1
    for (int j = 0; j < 64; j++) {
        unsigned k = key[j];
        bool eq = (k == T);
        unsigned em = __ballot_sync(0xFFFFFFFFu, eq);
        bool pick = eq && ((int)__popc(em & lmask) < rem);
        bool sel  = (k > T) || pick;
        if (sel) { selmask |= (1ull << j); if (k < kmin_in) kmin_in = k; }
        else     { if (k > kmax_out) kmax_out = k; }
        rem -= __popc(em);
        if (rem < 0) rem = 0;
    }
    kmin_in  = __reduce_min_sync(0xFFFFFFFFu, kmin_in);
    kmax_out = __reduce_max_sync(0xFFFFFFFFu, kmax_out);

    float vin  = key_decode(kmin_in);
    float vout = key_decode(kmax_out);

    // ---- exact fp64 re-ranking of the boundary, if ambiguous ----
    if (vin - vout < AMBIG_W) {
        float wlo = vout - AMBIG_W;
        float whi = vin + AMBIG_W;
        int ncand = 0;
#pragma unroll 1
        for (int j = 0; j < 64; j++) {
            float v = key_decode(key[j]);
            bool isc = (v >= wlo) && (v <= whi);
            unsigned bal = __ballot_sync(0xFFFFFFFFu, isc);
            if (isc) {
                int pos = ncand + __popc(bal & lmask);
                if (pos < MAXCAND) {
                    s_cidx[warp][pos] = j * 32 + lane;
                    s_csel[warp][pos] = (int)((selmask >> j) & 1ull);
                }
            }
            ncand += __popc(bal);
        }
        if (ncand > MAXCAND) ncand = MAXCAND;
        __syncwarp();

        // exact dots, deterministic fixed order
        const float* xr = x + (size_t)row * DIN;
        for (int c = 0; c < ncand; c++) {
            const float* wr = Wenc + (size_t)s_cidx[warp][c] * DIN;
            double s = 0.0;
#pragma unroll
            for (int t = 0; t < DIN / 32; t++) {
                int kk = lane + t * 32;
                s += (double)xr[kk] * (double)wr[kk];
            }
#pragma unroll
            for (int off = 16; off > 0; off >>= 1)
                s += __shfl_down_sync(0xFFFFFFFFu, s, off);
            if (lane == 0) s_cval[warp][c] = s;
            __syncwarp();
        }

        if (lane == 0) {
            int nkeep = 0;
            for (int c = 0; c < ncand; c++) nkeep += s_csel[warp][c];
            unsigned chosen = 0;
            for (int s = 0; s < nkeep; s++) {
                int best = -1;
                for (int c = 0; c < ncand; c++) {
                    if (chosen & (1u << c)) continue;
                    if (best < 0 ||
                        s_cval[warp][c] > s_cval[warp][best] ||
                        (s_cval[warp][c] == s_cval[warp][best] &&
                         s_cidx[warp][c] < s_cidx[warp][best]))
                        best = c;
                }
                chosen |= (1u << best);
            }
            s_chosen[warp] = chosen;
        }
        __syncwarp();
        unsigned chosen = s_chosen[warp];

        for (int c = 0; c < ncand; c++) {
            int fi = s_cidx[warp][c];
            if ((fi & 31) == lane) {
                int j = fi >> 5;
                if (chosen & (1u << c)) selmask |=  (1ull << j);
                else                    selmask &= ~(1ull << j);
            }
        }
        __syncwarp();
    }

    // ---- write dense h_sparse + compact lists ----
    float* orow = hsp + (size_t)row * DHID;
    int nsel = 0;
#pragma unroll 1
    for (int j = 0; j < 64; j++) {
        bool sel = (selmask >> j) & 1ull;
        unsigned k = key[j];
        float v = (k > 0x80000000u) ? __uint_as_float(k ^ 0x80000000u) : 0.0f;  // relu
        orow[j * 32 + lane] = sel ? v : 0.0f;

        unsigned sm = __ballot_sync(0xFFFFFFFFu, sel);
        if (sel) {
            int slot = nsel + __popc(sm & lmask);
            g_tidx[(size_t)row * TOPK + slot] = j * 32 + lane;
            g_tval[(size_t)row * TOPK + slot] = v;
        }
        nsel += __popc(sm);
    }
}

// ============================================================
// Sparse decoder: recon[row,:] = b_dec + sum_k val_k * Wt[idx_k,:]
// ============================================================
__global__ __launch_bounds__(192)
void decode_kernel(const float* __restrict__ bdec, float* __restrict__ recon)
{
    int row = blockIdx.x;
    int t = threadIdx.x;
    __shared__ float sval[TOPK];
    __shared__ int   sidx[TOPK];
    if (t < TOPK) {
        sval[t] = g_tval[(size_t)row * TOPK + t];
        sidx[t] = g_tidx[(size_t)row * TOPK + t];
    }
    __syncthreads();

    float4 acc = *(const float4*)&bdec[t * 4];
#pragma unroll 8
    for (int k = 0; k < TOPK; k++) {
        float v = sval[k];
        float4 w = *(const float4*)&g_Wt[(size_t)sidx[k] * DIN + t * 4];
        acc.x += v * w.x; acc.y += v * w.y; acc.z += v * w.z; acc.w += v * w.w;
    }
    *(float4*)&recon[(size_t)row * DIN + t * 4] = acc;
}

// ============================================================
extern "C" void kernel_launch(void* const* d_in, const int* in_sizes, int n_in,
                              void* d_out, int out_size)
{
    const float* x     = (const float*)d_in[0];
    const float* W_enc = (const float*)d_in[1];
    const float* b_enc = (const float*)d_in[2];
    const float* W_dec = (const float*)d_in[3];
    const float* b_dec = (const float*)d_in[4];

    float* out   = (float*)d_out;
    float* recon = out;                                 // [B, 768]
    float* hsp   = out + (size_t)BATCH * DIN;           // [B, 2048]
    float* hpre  = hsp + (size_t)BATCH * DHID;          // [B, 2048]

    transpose_kernel<<<dim3(DHID / 32, DIN / 32), dim3(32, 8)>>>(W_dec);
    gemm3xtf32<<<dim3(DHID / 128, BATCH / 128), 256>>>(x, W_enc, b_enc, hpre,
                                                       BATCH, DHID, DIN);
    topk_kernel<<<BATCH / 8, 256>>>(hpre, hsp, x, W_enc);
    decode_kernel<<<BATCH, 192>>>(b_dec, recon);
}

// round 3
// speedup vs baseline: 1.2183x; 1.2183x over previous
#include <cuda_runtime.h>
#include <cuda_bf16.h>
#include <mma.h>
#include <cstdint>

using namespace nvcuda;

#define BATCH 32768
#define DIN   768
#define DHID  2048
#define TOPK  32

// -------- scratch (no cudaMalloc allowed) --------
__device__ float g_Wt[(size_t)DHID * DIN];       // W_dec transposed: [2048][768]
__device__ int   g_tidx[(size_t)BATCH * TOPK];
__device__ float g_tval[(size_t)BATCH * TOPK];

// ============================================================
// W_dec [768][2048] -> g_Wt [2048][768]
// ============================================================
__global__ void transpose_kernel(const float* __restrict__ W)
{
    __shared__ float tile[32][33];
    int bx = blockIdx.x * 32;  // h
    int by = blockIdx.y * 32;  // d
    int tx = threadIdx.x, ty = threadIdx.y;
#pragma unroll
    for (int i = 0; i < 32; i += 8)
        tile[ty + i][tx] = W[(size_t)(by + ty + i) * DHID + bx + tx];
    __syncthreads();
#pragma unroll
    for (int i = 0; i < 32; i += 8)
        g_Wt[(size_t)(bx + ty + i) * DIN + by + tx] = tile[tx][ty + i];
}

// ============================================================
// Encoder GEMM, 3xTF32, cp.async 3-stage pipeline.
//   C[m,n] = sum_k A[m,k]*B[n,k] + bias[n]
// BM=BN=128, BK=32, 256 thr (8 warps, 4x2), warp tile 32x64.
// ============================================================
#define BK   32
#define LDS_ 36                        // BK + 4 pad (16B aligned rows)
#define ASZ  (128 * LDS_)              // floats per matrix per stage
#define STG  (2 * ASZ)                 // floats per stage (A + B)
#define NKT  (DIN / BK)                // 24 k-tiles

__device__ __forceinline__ void cp16(float* dst, const float* src)
{
    unsigned d = (unsigned)__cvta_generic_to_shared(dst);
    asm volatile("cp.async.cg.shared.global [%0], [%1], 16;\n" :: "r"(d), "l"(src));
}

__global__ __launch_bounds__(256)
void gemm3xtf32(const float* __restrict__ A, const float* __restrict__ Bmat,
                const float* __restrict__ bias, float* __restrict__ C)
{
    extern __shared__ float sm[];   // 3 stages * STG floats

    int tid  = threadIdx.x;
    int warp = tid >> 5;
    int wm   = warp & 3;
    int wn   = warp >> 2;
    int m0 = blockIdx.y * 128;
    int n0 = blockIdx.x * 128;

    using FragA = wmma::fragment<wmma::matrix_a, 16, 16, 8, wmma::precision::tf32, wmma::row_major>;
    using FragB = wmma::fragment<wmma::matrix_b, 16, 16, 8, wmma::precision::tf32, wmma::col_major>;
    using FragC = wmma::fragment<wmma::accumulator, 16, 16, 8, float>;

    // ---- bias init via smem broadcast tile (reuses stage-0 region) ----
    for (int i = tid; i < 16 * 128; i += 256)
        sm[i] = bias[n0 + (i & 127)];
    __syncthreads();

    FragC acc[2][4];
#pragma unroll
    for (int i = 0; i < 2; i++)
#pragma unroll
        for (int j = 0; j < 4; j++)
            wmma::load_matrix_sync(acc[i][j], &sm[wn * 64 + j * 16], 128, wmma::mem_row_major);
    __syncthreads();

    // per-thread load coords: 4 float4 per matrix per stage
    int r_ld[4], c_ld[4];
#pragma unroll
    for (int p = 0; p < 4; p++) {
        int f = tid + p * 256;          // 0..1023
        r_ld[p] = f >> 3;               // row 0..127
        c_ld[p] = (f & 7) * 4;          // col 0,4,..28
    }

    auto load_tile = [&](int buf, int kt) {
        float* As = sm + buf * STG;
        float* Bs = As + ASZ;
        int k0 = kt * BK;
#pragma unroll
        for (int p = 0; p < 4; p++) {
            int r = r_ld[p], c = c_ld[p];
            cp16(&As[r * LDS_ + c], &A[(size_t)(m0 + r) * DIN + k0 + c]);
            cp16(&Bs[r * LDS_ + c], &Bmat[(size_t)(n0 + r) * DIN + k0 + c]);
        }
        asm volatile("cp.async.commit_group;\n" ::);
    };

    // ---- prologue ----
    load_tile(0, 0);
    load_tile(1, 1);

    for (int t = 0; t < NKT; t++) {
        int tn = (t + 2 < NKT) ? t + 2 : 0;   // clamped dummy keeps group count uniform
        load_tile((t + 2) % 3, tn);

        asm volatile("cp.async.wait_group 2;\n" ::);
        __syncthreads();

        float* As = sm + (t % 3) * STG;
        float* Bs = As + ASZ;

#pragma unroll
        for (int ks = 0; ks < 4; ks++) {
            int ko = ks * 8;
            FragA ahi[2], alo[2];
#pragma unroll
            for (int i = 0; i < 2; i++) {
                wmma::load_matrix_sync(ahi[i], &As[(wm * 32 + i * 16) * LDS_ + ko], LDS_);
#pragma unroll
                for (int e = 0; e < ahi[i].num_elements; e++) {
                    float x = ahi[i].x[e];
                    float h = wmma::__float_to_tf32(x);
                    ahi[i].x[e] = h;
                    alo[i].x[e] = wmma::__float_to_tf32(x - h);
                }
            }
#pragma unroll
            for (int j = 0; j < 4; j++) {
                FragB bhi, blo;
                wmma::load_matrix_sync(bhi, &Bs[(wn * 64 + j * 16) * LDS_ + ko], LDS_);
#pragma unroll
                for (int e = 0; e < bhi.num_elements; e++) {
                    float x = bhi.x[e];
                    float h = wmma::__float_to_tf32(x);
                    bhi.x[e] = h;
                    blo.x[e] = wmma::__float_to_tf32(x - h);
                }
#pragma unroll
                for (int i = 0; i < 2; i++) {
                    wmma::mma_sync(acc[i][j], ahi[i], blo, acc[i][j]);
                    wmma::mma_sync(acc[i][j], alo[i], bhi, acc[i][j]);
                    wmma::mma_sync(acc[i][j], ahi[i], bhi, acc[i][j]);
                }
            }
        }
        __syncthreads();
    }

#pragma unroll
    for (int i = 0; i < 2; i++)
#pragma unroll
        for (int j = 0; j < 4; j++) {
            float* cp = &C[(size_t)(m0 + wm * 32 + i * 16) * DHID + n0 + wn * 64 + j * 16];
            wmma::store_matrix_sync(cp, acc[i][j], DHID, wmma::mem_row_major);
        }
}

// ============================================================
// Top-K with exact fp64 re-ranking of the ambiguous boundary.
// ============================================================
#define AMBIG_W 1e-4f
#define MAXCAND 16

__device__ __forceinline__ float key_decode(unsigned k)
{
    return (k >= 0x80000000u) ? __uint_as_float(k ^ 0x80000000u)
                              : __uint_as_float(~k);
}

__global__ __launch_bounds__(256)
void topk_kernel(const float* __restrict__ hpre, float* __restrict__ hsp,
                 const float* __restrict__ x, const float* __restrict__ Wenc)
{
    int lane = threadIdx.x & 31;
    int warp = threadIdx.x >> 5;
    int row  = blockIdx.x * 8 + warp;
    const float* p = hpre + (size_t)row * DHID;

    __shared__ int    s_cidx[8][MAXCAND];
    __shared__ double s_cval[8][MAXCAND];
    __shared__ int    s_csel[8][MAXCAND];
    __shared__ unsigned s_chosen[8];

    unsigned key[64];
#pragma unroll
    for (int j = 0; j < 64; j++) {
        unsigned u = __float_as_uint(p[j * 32 + lane]);
        key[j] = (u & 0x80000000u) ? ~u : (u | 0x80000000u);
    }

    unsigned lo = 0u, hi = 0xFFFFFFFFu;
#pragma unroll 1
    for (int it = 0; it < 32; ++it) {
        if (lo >= hi) break;
        unsigned span = hi - lo;
        unsigned mid = lo + (span >> 1) + (span & 1u);
        int c = 0;
#pragma unroll
        for (int j = 0; j < 64; j++) c += (key[j] >= mid) ? 1 : 0;
        c = __reduce_add_sync(0xFFFFFFFFu, c);
        if (c >= TOPK) lo = mid; else hi = mid - 1;
    }
    unsigned T = lo;

    int cg = 0;
#pragma unroll
    for (int j = 0; j < 64; j++) cg += (key[j] > T) ? 1 : 0;
    cg = __reduce_add_sync(0xFFFFFFFFu, cg);
    int rem = TOPK - cg;

    unsigned lmask = (1u << lane) - 1u;
    unsigned long long selmask = 0ull;
    unsigned kmin_in = 0xFFFFFFFFu;
    unsigned kmax_out = 0u;
#pragma unroll 1
    for (int j = 0; j < 64; j++) {
        unsigned k = key[j];
        bool eq = (k == T);
        unsigned em = __ballot_sync(0xFFFFFFFFu, eq);
        bool pick = eq && ((int)__popc(em & lmask) < rem);
        bool sel  = (k > T) || pick;
        if (sel) { selmask |= (1ull << j); if (k < kmin_in) kmin_in = k; }
        else     { if (k > kmax_out) kmax_out = k; }
        rem -= __popc(em);
        if (rem < 0) rem = 0;
    }
    kmin_in  = __reduce_min_sync(0xFFFFFFFFu, kmin_in);
    kmax_out = __reduce_max_sync(0xFFFFFFFFu, kmax_out);

    float vin  = key_decode(kmin_in);
    float vout = key_decode(kmax_out);

    if (vin - vout < AMBIG_W) {
        float wlo = vout - AMBIG_W;
        float whi = vin + AMBIG_W;
        int ncand = 0;
#pragma unroll 1
        for (int j = 0; j < 64; j++) {
            float v = key_decode(key[j]);
            bool isc = (v >= wlo) && (v <= whi);
            unsigned bal = __ballot_sync(0xFFFFFFFFu, isc);
            if (isc) {
                int pos = ncand + __popc(bal & lmask);
                if (pos < MAXCAND) {
                    s_cidx[warp][pos] = j * 32 + lane;
                    s_csel[warp][pos] = (int)((selmask >> j) & 1ull);
                }
            }
            ncand += __popc(bal);
        }
        if (ncand > MAXCAND) ncand = MAXCAND;
        __syncwarp();

        const float* xr = x + (size_t)row * DIN;
        for (int c = 0; c < ncand; c++) {
            const float* wr = Wenc + (size_t)s_cidx[warp][c] * DIN;
            double s = 0.0;
#pragma unroll
            for (int t = 0; t < DIN / 32; t++) {
                int kk = lane + t * 32;
                s += (double)xr[kk] * (double)wr[kk];
            }
#pragma unroll
            for (int off = 16; off > 0; off >>= 1)
                s += __shfl_down_sync(0xFFFFFFFFu, s, off);
            if (lane == 0) s_cval[warp][c] = s;
            __syncwarp();
        }

        if (lane == 0) {
            int nkeep = 0;
            for (int c = 0; c < ncand; c++) nkeep += s_csel[warp][c];
            unsigned chosen = 0;
            for (int s = 0; s < nkeep; s++) {
                int best = -1;
                for (int c = 0; c < ncand; c++) {
                    if (chosen & (1u << c)) continue;
                    if (best < 0 ||
                        s_cval[warp][c] > s_cval[warp][best] ||
                        (s_cval[warp][c] == s_cval[warp][best] &&
                         s_cidx[warp][c] < s_cidx[warp][best]))
                        best = c;
                }
                chosen |= (1u << best);
            }
            s_chosen[warp] = chosen;
        }
        __syncwarp();
        unsigned chosen = s_chosen[warp];

        for (int c = 0; c < ncand; c++) {
            int fi = s_cidx[warp][c];
            if ((fi & 31) == lane) {
                int j = fi >> 5;
                if (chosen & (1u << c)) selmask |=  (1ull << j);
                else                    selmask &= ~(1ull << j);
            }
        }
        __syncwarp();
    }

    float* orow = hsp + (size_t)row * DHID;
    int nsel = 0;
#pragma unroll 1
    for (int j = 0; j < 64; j++) {
        bool sel = (selmask >> j) & 1ull;
        unsigned k = key[j];
        float v = (k > 0x80000000u) ? __uint_as_float(k ^ 0x80000000u) : 0.0f;
        orow[j * 32 + lane] = sel ? v : 0.0f;

        unsigned sm2 = __ballot_sync(0xFFFFFFFFu, sel);
        if (sel) {
            int slot = nsel + __popc(sm2 & lmask);
            g_tidx[(size_t)row * TOPK + slot] = j * 32 + lane;
            g_tval[(size_t)row * TOPK + slot] = v;
        }
        nsel += __popc(sm2);
    }
}

// ============================================================
// Sparse decoder: recon[row,:] = b_dec + sum_k val_k * Wt[idx_k,:]
// ============================================================
__global__ __launch_bounds__(192)
void decode_kernel(const float* __restrict__ bdec, float* __restrict__ recon)
{
    int row = blockIdx.x;
    int t = threadIdx.x;
    __shared__ float sval[TOPK];
    __shared__ int   sidx[TOPK];
    if (t < TOPK) {
        sval[t] = g_tval[(size_t)row * TOPK + t];
        sidx[t] = g_tidx[(size_t)row * TOPK + t];
    }
    __syncthreads();

    float4 acc = *(const float4*)&bdec[t * 4];
#pragma unroll 8
    for (int k = 0; k < TOPK; k++) {
        float v = sval[k];
        float4 w = *(const float4*)&g_Wt[(size_t)sidx[k] * DIN + t * 4];
        acc.x += v * w.x; acc.y += v * w.y; acc.z += v * w.z; acc.w += v * w.w;
    }
    *(float4*)&recon[(size_t)row * DIN + t * 4] = acc;
}

// ============================================================
extern "C" void kernel_launch(void* const* d_in, const int* in_sizes, int n_in,
                              void* d_out, int out_size)
{
    const float* x     = (const float*)d_in[0];
    const float* W_enc = (const float*)d_in[1];
    const float* b_enc = (const float*)d_in[2];
    const float* W_dec = (const float*)d_in[3];
    const float* b_dec = (const float*)d_in[4];

    float* out   = (float*)d_out;
    float* recon = out;                                 // [B, 768]
    float* hsp   = out + (size_t)BATCH * DIN;           // [B, 2048]
    float* hpre  = hsp + (size_t)BATCH * DHID;          // [B, 2048]

    const int smem_bytes = 3 * STG * sizeof(float);     // 110,592 B
    cudaFuncSetAttribute(gemm3xtf32, cudaFuncAttributeMaxDynamicSharedMemorySize, smem_bytes);

    transpose_kernel<<<dim3(DHID / 32, DIN / 32), dim3(32, 8)>>>(W_dec);
    gemm3xtf32<<<dim3(DHID / 128, BATCH / 128), 256, smem_bytes>>>(x, W_enc, b_enc, hpre);
    topk_kernel<<<BATCH / 8, 256>>>(hpre, hsp, x, W_enc);
    decode_kernel<<<BATCH, 192>>>(b_dec, recon);
}

// round 4
// speedup vs baseline: 2.4954x; 2.0482x over previous
#include <cuda_runtime.h>
#include <cuda_bf16.h>
#include <mma.h>
#include <cstdint>

using namespace nvcuda;

#define BATCH 32768
#define DIN   768
#define DHID  2048
#define TOPK  32

// -------- scratch (no cudaMalloc allowed) --------
__device__ __align__(16) float g_Wt[(size_t)DHID * DIN];   // W_dec^T [2048][768]
__device__ int   g_tidx[(size_t)BATCH * TOPK];
__device__ float g_tval[(size_t)BATCH * TOPK];
__device__ __align__(16) __nv_bfloat16 g_Ah[(size_t)BATCH * DIN];
__device__ __align__(16) __nv_bfloat16 g_Al[(size_t)BATCH * DIN];
__device__ __align__(16) __nv_bfloat16 g_Bh[(size_t)DHID * DIN];
__device__ __align__(16) __nv_bfloat16 g_Bl[(size_t)DHID * DIN];

// ============================================================
// f32 -> (hi, lo) bf16 split.  2 floats per thread, coalesced.
// ============================================================
__global__ __launch_bounds__(256)
void split_kernel(const float* __restrict__ src,
                  __nv_bfloat16* __restrict__ hi,
                  __nv_bfloat16* __restrict__ lo)
{
    int i = blockIdx.x * 256 + threadIdx.x;     // pair index
    float2 v = ((const float2*)src)[i];
    __nv_bfloat16 h0 = __float2bfloat16(v.x);
    __nv_bfloat16 h1 = __float2bfloat16(v.y);
    __nv_bfloat16 l0 = __float2bfloat16(v.x - __bfloat162float(h0));
    __nv_bfloat16 l1 = __float2bfloat16(v.y - __bfloat162float(h1));
    ((__nv_bfloat162*)hi)[i] = __halves2bfloat162(h0, h1);
    ((__nv_bfloat162*)lo)[i] = __halves2bfloat162(l0, l1);
}

// ============================================================
// W_dec [768][2048] -> g_Wt [2048][768]
// ============================================================
__global__ void transpose_kernel(const float* __restrict__ W)
{
    __shared__ float tile[32][33];
    int bx = blockIdx.x * 32, by = blockIdx.y * 32;
    int tx = threadIdx.x, ty = threadIdx.y;
#pragma unroll
    for (int i = 0; i < 32; i += 8)
        tile[ty + i][tx] = W[(size_t)(by + ty + i) * DHID + bx + tx];
    __syncthreads();
#pragma unroll
    for (int i = 0; i < 32; i += 8)
        g_Wt[(size_t)(bx + ty + i) * DIN + by + tx] = tile[tx][ty + i];
}

// ============================================================
// Encoder GEMM, bf16 3-split, cp.async 2-stage pipeline.
//   C[m,n] = sum_k A[m,k]*B[n,k] + bias[n]
// BM=BN=128, BK=32, 256 thr (8 warps 4x2), warp tile 32x64.
// smem stage: Ah|Al|Bh|Bl, each 128 rows x 40 halves (pad 8).
// ============================================================
#define BK    32
#define HS    40                       // halves per row (32 + 8 pad)
#define PART  (128 * HS)               // halves per matrix part
#define STG_H (4 * PART)               // halves per stage
#define NKT   (DIN / BK)               // 24

__device__ __forceinline__ void cp16(__nv_bfloat16* dst, const __nv_bfloat16* src)
{
    unsigned d = (unsigned)__cvta_generic_to_shared(dst);
    asm volatile("cp.async.cg.shared.global [%0], [%1], 16;\n" :: "r"(d), "l"(src));
}

__global__ __launch_bounds__(256)
void gemm_bf16x3(const float* __restrict__ bias, float* __restrict__ C)
{
    extern __shared__ __nv_bfloat16 smh[];   // 2 stages * STG_H halves

    int tid  = threadIdx.x;
    int warp = tid >> 5;
    int wm   = warp & 3;
    int wn   = warp >> 2;
    int m0 = blockIdx.y * 128;
    int n0 = blockIdx.x * 128;

    using FragA = wmma::fragment<wmma::matrix_a, 16, 16, 16, __nv_bfloat16, wmma::row_major>;
    using FragB = wmma::fragment<wmma::matrix_b, 16, 16, 16, __nv_bfloat16, wmma::col_major>;
    using FragC = wmma::fragment<wmma::accumulator, 16, 16, 16, float>;

    // ---- bias init via smem f32 broadcast tile (reuses stage region) ----
    float* bsm = (float*)smh;
    for (int i = tid; i < 16 * 128; i += 256)
        bsm[i] = bias[n0 + (i & 127)];
    __syncthreads();

    FragC acc[2][4];
#pragma unroll
    for (int i = 0; i < 2; i++)
#pragma unroll
        for (int j = 0; j < 4; j++)
            wmma::load_matrix_sync(acc[i][j], &bsm[wn * 64 + j * 16], 128, wmma::mem_row_major);
    __syncthreads();

    auto load_tile = [&](int buf, int kt) {
        __nv_bfloat16* s = smh + buf * STG_H;
        int k0 = kt * BK;
#pragma unroll
        for (int p = 0; p < 2; p++) {
            int f  = tid + p * 256;      // 0..511
            int r  = f >> 2;             // 0..127
            int ch = (f & 3) * 8;        // halves offset 0,8,16,24
            size_t ga = (size_t)(m0 + r) * DIN + k0 + ch;
            size_t gb = (size_t)(n0 + r) * DIN + k0 + ch;
            cp16(&s[0 * PART + r * HS + ch], &g_Ah[ga]);
            cp16(&s[1 * PART + r * HS + ch], &g_Al[ga]);
            cp16(&s[2 * PART + r * HS + ch], &g_Bh[gb]);
            cp16(&s[3 * PART + r * HS + ch], &g_Bl[gb]);
        }
        asm volatile("cp.async.commit_group;\n" ::);
    };

    load_tile(0, 0);

    for (int t = 0; t < NKT; t++) {
        load_tile((t + 1) & 1, (t + 1 < NKT) ? t + 1 : 0);
        asm volatile("cp.async.wait_group 1;\n" ::);
        __syncthreads();

        __nv_bfloat16* s  = smh + (t & 1) * STG_H;
        __nv_bfloat16* Ah = s;
        __nv_bfloat16* Al = s + PART;
        __nv_bfloat16* Bh = s + 2 * PART;
        __nv_bfloat16* Bl = s + 3 * PART;

#pragma unroll
        for (int ks = 0; ks < BK; ks += 16) {
            FragA ah[2], al[2];
#pragma unroll
            for (int i = 0; i < 2; i++) {
                wmma::load_matrix_sync(ah[i], &Ah[(wm * 32 + i * 16) * HS + ks], HS);
                wmma::load_matrix_sync(al[i], &Al[(wm * 32 + i * 16) * HS + ks], HS);
            }
#pragma unroll
            for (int j = 0; j < 4; j++) {
                FragB bh, bl;
                wmma::load_matrix_sync(bh, &Bh[(wn * 64 + j * 16) * HS + ks], HS);
                wmma::load_matrix_sync(bl, &Bl[(wn * 64 + j * 16) * HS + ks], HS);
#pragma unroll
                for (int i = 0; i < 2; i++) {
                    wmma::mma_sync(acc[i][j], ah[i], bl, acc[i][j]);
                    wmma::mma_sync(acc[i][j], al[i], bh, acc[i][j]);
                    wmma::mma_sync(acc[i][j], ah[i], bh, acc[i][j]);
                }
            }
        }
        __syncthreads();
    }

#pragma unroll
    for (int i = 0; i < 2; i++)
#pragma unroll
        for (int j = 0; j < 4; j++) {
            float* cp = &C[(size_t)(m0 + wm * 32 + i * 16) * DHID + n0 + wn * 64 + j * 16];
            wmma::store_matrix_sync(cp, acc[i][j], DHID, wmma::mem_row_major);
        }
}

// ============================================================
// Top-K with exact fp64 re-ranking of the ambiguous boundary.
// ============================================================
#define AMBIG_W 1e-4f
#define MAXCAND 16

__device__ __forceinline__ float key_decode(unsigned k)
{
    return (k >= 0x80000000u) ? __uint_as_float(k ^ 0x80000000u)
                              : __uint_as_float(~k);
}

__global__ __launch_bounds__(256)
void topk_kernel(const float* __restrict__ hpre, float* __restrict__ hsp,
                 const float* __restrict__ x, const float* __restrict__ Wenc)
{
    int lane = threadIdx.x & 31;
    int warp = threadIdx.x >> 5;
    int row  = blockIdx.x * 8 + warp;
    const float* p = hpre + (size_t)row * DHID;

    __shared__ int    s_cidx[8][MAXCAND];
    __shared__ double s_cval[8][MAXCAND];
    __shared__ int    s_csel[8][MAXCAND];
    __shared__ unsigned s_chosen[8];

    unsigned key[64];
#pragma unroll
    for (int j = 0; j < 64; j++) {
        unsigned u = __float_as_uint(p[j * 32 + lane]);
        key[j] = (u & 0x80000000u) ? ~u : (u | 0x80000000u);
    }

    unsigned lo = 0u, hi = 0xFFFFFFFFu;
#pragma unroll 1
    for (int it = 0; it < 32; ++it) {
        if (lo >= hi) break;
        unsigned span = hi - lo;
        unsigned mid = lo + (span >> 1) + (span & 1u);
        int c = 0;
#pragma unroll
        for (int j = 0; j < 64; j++) c += (key[j] >= mid) ? 1 : 0;
        c = __reduce_add_sync(0xFFFFFFFFu, c);
        if (c >= TOPK) lo = mid; else hi = mid - 1;
    }
    unsigned T = lo;

    int cg = 0;
#pragma unroll
    for (int j = 0; j < 64; j++) cg += (key[j] > T) ? 1 : 0;
    cg = __reduce_add_sync(0xFFFFFFFFu, cg);
    int rem = TOPK - cg;

    unsigned lmask = (1u << lane) - 1u;
    unsigned long long selmask = 0ull;
    unsigned kmin_in = 0xFFFFFFFFu;
    unsigned kmax_out = 0u;
#pragma unroll 1
    for (int j = 0; j < 64; j++) {
        unsigned k = key[j];
        bool eq = (k == T);
        unsigned em = __ballot_sync(0xFFFFFFFFu, eq);
        bool pick = eq && ((int)__popc(em & lmask) < rem);
        bool sel  = (k > T) || pick;
        if (sel) { selmask |= (1ull << j); if (k < kmin_in) kmin_in = k; }
        else     { if (k > kmax_out) kmax_out = k; }
        rem -= __popc(em);
        if (rem < 0) rem = 0;
    }
    kmin_in  = __reduce_min_sync(0xFFFFFFFFu, kmin_in);
    kmax_out = __reduce_max_sync(0xFFFFFFFFu, kmax_out);

    float vin  = key_decode(kmin_in);
    float vout = key_decode(kmax_out);

    if (vin - vout < AMBIG_W) {
        float wlo = vout - AMBIG_W;
        float whi = vin + AMBIG_W;
        int ncand = 0;
#pragma unroll 1
        for (int j = 0; j < 64; j++) {
            float v = key_decode(key[j]);
            bool isc = (v >= wlo) && (v <= whi);
            unsigned bal = __ballot_sync(0xFFFFFFFFu, isc);
            if (isc) {
                int pos = ncand + __popc(bal & lmask);
                if (pos < MAXCAND) {
                    s_cidx[warp][pos] = j * 32 + lane;
                    s_csel[warp][pos] = (int)((selmask >> j) & 1ull);
                }
            }
            ncand += __popc(bal);
        }
        if (ncand > MAXCAND) ncand = MAXCAND;
        __syncwarp();

        const float* xr = x + (size_t)row * DIN;
        for (int c = 0; c < ncand; c++) {
            const float* wr = Wenc + (size_t)s_cidx[warp][c] * DIN;
            double s = 0.0;
#pragma unroll
            for (int t = 0; t < DIN / 32; t++) {
                int kk = lane + t * 32;
                s += (double)xr[kk] * (double)wr[kk];
            }
#pragma unroll
            for (int off = 16; off > 0; off >>= 1)
                s += __shfl_down_sync(0xFFFFFFFFu, s, off);
            if (lane == 0) s_cval[warp][c] = s;
            __syncwarp();
        }

        if (lane == 0) {
            int nkeep = 0;
            for (int c = 0; c < ncand; c++) nkeep += s_csel[warp][c];
            unsigned chosen = 0;
            for (int s = 0; s < nkeep; s++) {
                int best = -1;
                for (int c = 0; c < ncand; c++) {
                    if (chosen & (1u << c)) continue;
                    if (best < 0 ||
                        s_cval[warp][c] > s_cval[warp][best] ||
                        (s_cval[warp][c] == s_cval[warp][best] &&
                         s_cidx[warp][c] < s_cidx[warp][best]))
                        best = c;
                }
                chosen |= (1u << best);
            }
            s_chosen[warp] = chosen;
        }
        __syncwarp();
        unsigned chosen = s_chosen[warp];

        for (int c = 0; c < ncand; c++) {
            int fi = s_cidx[warp][c];
            if ((fi & 31) == lane) {
                int j = fi >> 5;
                if (chosen & (1u << c)) selmask |=  (1ull << j);
                else                    selmask &= ~(1ull << j);
            }
        }
        __syncwarp();
    }

    float* orow = hsp + (size_t)row * DHID;
    int nsel = 0;
#pragma unroll 1
    for (int j = 0; j < 64; j++) {
        bool sel = (selmask >> j) & 1ull;
        unsigned k = key[j];
        float v = (k > 0x80000000u) ? __uint_as_float(k ^ 0x80000000u) : 0.0f;
        orow[j * 32 + lane] = sel ? v : 0.0f;

        unsigned sm2 = __ballot_sync(0xFFFFFFFFu, sel);
        if (sel) {
            int slot = nsel + __popc(sm2 & lmask);
            g_tidx[(size_t)row * TOPK + slot] = j * 32 + lane;
            g_tval[(size_t)row * TOPK + slot] = v;
        }
        nsel += __popc(sm2);
    }
}

// ============================================================
// Sparse decoder: recon[row,:] = b_dec + sum_k val_k * Wt[idx_k,:]
// ============================================================
__global__ __launch_bounds__(192)
void decode_kernel(const float* __restrict__ bdec, float* __restrict__ recon)
{
    int row = blockIdx.x;
    int t = threadIdx.x;
    __shared__ float sval[TOPK];
    __shared__ int   sidx[TOPK];
    if (t < TOPK) {
        sval[t] = g_tval[(size_t)row * TOPK + t];
        sidx[t] = g_tidx[(size_t)row * TOPK + t];
    }
    __syncthreads();

    float4 acc = *(const float4*)&bdec[t * 4];
#pragma unroll 8
    for (int k = 0; k < TOPK; k++) {
        float v = sval[k];
        float4 w = *(const float4*)&g_Wt[(size_t)sidx[k] * DIN + t * 4];
        acc.x += v * w.x; acc.y += v * w.y; acc.z += v * w.z; acc.w += v * w.w;
    }
    *(float4*)&recon[(size_t)row * DIN + t * 4] = acc;
}

// ============================================================
extern "C" void kernel_launch(void* const* d_in, const int* in_sizes, int n_in,
                              void* d_out, int out_size)
{
    const float* x     = (const float*)d_in[0];
    const float* W_enc = (const float*)d_in[1];
    const float* b_enc = (const float*)d_in[2];
    const float* W_dec = (const float*)d_in[3];
    const float* b_dec = (const float*)d_in[4];

    float* out   = (float*)d_out;
    float* recon = out;                                 // [B, 768]
    float* hsp   = out + (size_t)BATCH * DIN;           // [B, 2048]
    float* hpre  = hsp + (size_t)BATCH * DHID;          // [B, 2048]

    __nv_bfloat16 *ah, *al, *bh, *bl;
    cudaGetSymbolAddress((void**)&ah, g_Ah);
    cudaGetSymbolAddress((void**)&al, g_Al);
    cudaGetSymbolAddress((void**)&bh, g_Bh);
    cudaGetSymbolAddress((void**)&bl, g_Bl);

    const int smem_bytes = 2 * STG_H * sizeof(__nv_bfloat16);   // 81,920 B
    static bool attr_set = false;
    cudaFuncSetAttribute(gemm_bf16x3, cudaFuncAttributeMaxDynamicSharedMemorySize, smem_bytes);
    (void)attr_set;

    split_kernel<<<(BATCH * DIN / 2) / 256, 256>>>(x, ah, al);
    split_kernel<<<(DHID * DIN / 2) / 256, 256>>>(W_enc, bh, bl);
    transpose_kernel<<<dim3(DHID / 32, DIN / 32), dim3(32, 8)>>>(W_dec);
    gemm_bf16x3<<<dim3(DHID / 128, BATCH / 128), 256, smem_bytes>>>(b_enc, hpre);
    topk_kernel<<<BATCH / 8, 256>>>(hpre, hsp, x, W_enc);
    decode_kernel<<<BATCH, 192>>>(b_dec, recon);
}

// round 6
// speedup vs baseline: 2.6422x; 1.0588x over previous
#include <cuda_runtime.h>
#include <cuda_bf16.h>
#include <mma.h>
#include <cstdint>

using namespace nvcuda;

#define BATCH 32768
#define DIN   768
#define DHID  2048
#define TOPK  32

// -------- scratch (no cudaMalloc allowed) --------
__device__ __align__(16) float g_Wt[(size_t)DHID * DIN];   // W_dec^T [2048][768]
__device__ int   g_tidx[(size_t)BATCH * TOPK];
__device__ float g_tval[(size_t)BATCH * TOPK];
__device__ __align__(16) __nv_bfloat16 g_Ah[(size_t)BATCH * DIN];
__device__ __align__(16) __nv_bfloat16 g_Al[(size_t)BATCH * DIN];
__device__ __align__(16) __nv_bfloat16 g_Bh[(size_t)DHID * DIN];
__device__ __align__(16) __nv_bfloat16 g_Bl[(size_t)DHID * DIN];

// ============================================================
// f32 -> (hi, lo) bf16 split
// ============================================================
__global__ __launch_bounds__(256)
void split_kernel(const float* __restrict__ src,
                  __nv_bfloat16* __restrict__ hi,
                  __nv_bfloat16* __restrict__ lo)
{
    int i = blockIdx.x * 256 + threadIdx.x;
    float2 v = ((const float2*)src)[i];
    __nv_bfloat16 h0 = __float2bfloat16(v.x);
    __nv_bfloat16 h1 = __float2bfloat16(v.y);
    __nv_bfloat16 l0 = __float2bfloat16(v.x - __bfloat162float(h0));
    __nv_bfloat16 l1 = __float2bfloat16(v.y - __bfloat162float(h1));
    ((__nv_bfloat162*)hi)[i] = __halves2bfloat162(h0, h1);
    ((__nv_bfloat162*)lo)[i] = __halves2bfloat162(l0, l1);
}

// ============================================================
// W_dec [768][2048] -> g_Wt [2048][768]
// ============================================================
__global__ void transpose_kernel(const float* __restrict__ W)
{
    __shared__ float tile[32][33];
    int bx = blockIdx.x * 32, by = blockIdx.y * 32;
    int tx = threadIdx.x, ty = threadIdx.y;
#pragma unroll
    for (int i = 0; i < 32; i += 8)
        tile[ty + i][tx] = W[(size_t)(by + ty + i) * DHID + bx + tx];
    __syncthreads();
#pragma unroll
    for (int i = 0; i < 32; i += 8)
        g_Wt[(size_t)(bx + ty + i) * DIN + by + tx] = tile[tx][ty + i];
}

// ============================================================
// Encoder GEMM, bf16 3-split, cp.async 3-stage pipeline.
//   C[m,n] = sum_k A[m,k]*B[n,k] + bias[n]
// Block 128x256, BK=32, 512 thr (16 warps 4x4), warp tile 32x64.
// Stage: Ah(128x40)|Al(128x40)|Bh(256x40)|Bl(256x40) halves.
// ============================================================
#define BK     32
#define HS     40                        // halves per row (32 + 8 pad)
#define A_PART (128 * HS)                // 5120 halves
#define B_PART (256 * HS)                // 10240 halves
#define STG_H  (2 * A_PART + 2 * B_PART) // 30720 halves / stage
#define NKT    (DIN / BK)                // 24
#define GEMM_SMEM (3 * STG_H * sizeof(__nv_bfloat16))   // 184320 B

__device__ __forceinline__ void cp16(__nv_bfloat16* dst, const __nv_bfloat16* src)
{
    unsigned d = (unsigned)__cvta_generic_to_shared(dst);
    asm volatile("cp.async.cg.shared.global [%0], [%1], 16;\n" :: "r"(d), "l"(src));
}

__global__ __launch_bounds__(512)
void gemm_bf16x3(const float* __restrict__ bias, float* __restrict__ C)
{
    extern __shared__ __nv_bfloat16 smh[];   // 3 stages

    int tid  = threadIdx.x;
    int warp = tid >> 5;
    int wm   = warp & 3;         // 0..3  (M slab, 32 rows)
    int wn   = warp >> 2;        // 0..3  (N slab, 64 cols)
    int m0 = blockIdx.y * 128;
    int n0 = blockIdx.x * 256;

    using FragA = wmma::fragment<wmma::matrix_a, 16, 16, 16, __nv_bfloat16, wmma::row_major>;
    using FragB = wmma::fragment<wmma::matrix_b, 16, 16, 16, __nv_bfloat16, wmma::col_major>;
    using FragC = wmma::fragment<wmma::accumulator, 16, 16, 16, float>;

    // ---- bias init via smem f32 broadcast tile (reuses stage region) ----
    float* bsm = (float*)smh;
    for (int i = tid; i < 16 * 256; i += 512)
        bsm[i] = bias[n0 + (i & 255)];
    __syncthreads();

    FragC acc[2][4];
#pragma unroll
    for (int i = 0; i < 2; i++)
#pragma unroll
        for (int j = 0; j < 4; j++)
            wmma::load_matrix_sync(acc[i][j], &bsm[wn * 64 + j * 16], 256, wmma::mem_row_major);
    __syncthreads();

    auto load_tile = [&](int buf, int kt) {
        __nv_bfloat16* s = smh + buf * STG_H;
        int k0 = kt * BK;
        // A parts: 128 rows x 4 cp16 = 512 ops = 1/thread/part
        {
            int r  = tid >> 2;
            int ch = (tid & 3) * 8;
            size_t ga = (size_t)(m0 + r) * DIN + k0 + ch;
            cp16(&s[0 * A_PART + r * HS + ch], &g_Ah[ga]);
            cp16(&s[1 * A_PART + r * HS + ch], &g_Al[ga]);
        }
        // B parts: 256 rows x 4 cp16 = 1024 ops = 2/thread/part
#pragma unroll
        for (int p = 0; p < 2; p++) {
            int f  = tid + p * 512;
            int r  = f >> 2;
            int ch = (f & 3) * 8;
            size_t gb = (size_t)(n0 + r) * DIN + k0 + ch;
            cp16(&s[2 * A_PART + r * HS + ch],          &g_Bh[gb]);
            cp16(&s[2 * A_PART + B_PART + r * HS + ch], &g_Bl[gb]);
        }
        asm volatile("cp.async.commit_group;\n" ::);
    };

    // ---- prologue: 2 stages in flight ----
    load_tile(0, 0);
    load_tile(1, 1);

    for (int t = 0; t < NKT; t++) {
        if (t + 2 < NKT) load_tile((t + 2) % 3, t + 2);
        else             asm volatile("cp.async.commit_group;\n" ::);

        asm volatile("cp.async.wait_group 2;\n" ::);
        __syncthreads();

        __nv_bfloat16* s  = smh + (t % 3) * STG_H;
        __nv_bfloat16* Ah = s;
        __nv_bfloat16* Al = s + A_PART;
        __nv_bfloat16* Bh = s + 2 * A_PART;
        __nv_bfloat16* Bl = s + 2 * A_PART + B_PART;

#pragma unroll
        for (int ks = 0; ks < BK; ks += 16) {
            FragA ah[2], al[2];
#pragma unroll
            for (int i = 0; i < 2; i++) {
                wmma::load_matrix_sync(ah[i], &Ah[(wm * 32 + i * 16) * HS + ks], HS);
                wmma::load_matrix_sync(al[i], &Al[(wm * 32 + i * 16) * HS + ks], HS);
            }
#pragma unroll
            for (int j = 0; j < 4; j++) {
                FragB bh, bl;
                wmma::load_matrix_sync(bh, &Bh[(wn * 64 + j * 16) * HS + ks], HS);
                wmma::load_matrix_sync(bl, &Bl[(wn * 64 + j * 16) * HS + ks], HS);
#pragma unroll
                for (int i = 0; i < 2; i++) {
                    wmma::mma_sync(acc[i][j], ah[i], bl, acc[i][j]);
                    wmma::mma_sync(acc[i][j], al[i], bh, acc[i][j]);
                    wmma::mma_sync(acc[i][j], ah[i], bh, acc[i][j]);
                }
            }
        }
        __syncthreads();
    }

#pragma unroll
    for (int i = 0; i < 2; i++)
#pragma unroll
        for (int j = 0; j < 4; j++) {
            float* cp = &C[(size_t)(m0 + wm * 32 + i * 16) * DHID + n0 + wn * 64 + j * 16];
            wmma::store_matrix_sync(cp, acc[i][j], DHID, wmma::mem_row_major);
        }
}

// ============================================================
// Top-K with exact fp64 re-ranking of the ambiguous boundary.
// ============================================================
#define AMBIG_W 1e-4f
#define MAXCAND 16

__device__ __forceinline__ float key_decode(unsigned k)
{
    return (k >= 0x80000000u) ? __uint_as_float(k ^ 0x80000000u)
                              : __uint_as_float(~k);
}

__global__ __launch_bounds__(256)
void topk_kernel(const float* __restrict__ hpre, float* __restrict__ hsp,
                 const float* __restrict__ x, const float* __restrict__ Wenc)
{
    int lane = threadIdx.x & 31;
    int warp = threadIdx.x >> 5;
    int row  = blockIdx.x * 8 + warp;
    const float* p = hpre + (size_t)row * DHID;

    __shared__ int    s_cidx[8][MAXCAND];
    __shared__ double s_cval[8][MAXCAND];
    __shared__ int    s_csel[8][MAXCAND];
    __shared__ unsigned s_chosen[8];

    unsigned key[64];
#pragma unroll
    for (int j = 0; j < 64; j++) {
        unsigned u = __float_as_uint(p[j * 32 + lane]);
        key[j] = (u & 0x80000000u) ? ~u : (u | 0x80000000u);
    }

    unsigned lo = 0u, hi = 0xFFFFFFFFu;
#pragma unroll 1
    for (int it = 0; it < 32; ++it) {
        if (lo >= hi) break;
        unsigned span = hi - lo;
        unsigned mid = lo + (span >> 1) + (span & 1u);
        int c = 0;
#pragma unroll
        for (int j = 0; j < 64; j++) c += (key[j] >= mid) ? 1 : 0;
        c = __reduce_add_sync(0xFFFFFFFFu, c);
        if (c >= TOPK) lo = mid; else hi = mid - 1;
    }
    unsigned T = lo;

    int cg = 0;
#pragma unroll
    for (int j = 0; j < 64; j++) cg += (key[j] > T) ? 1 : 0;
    cg = __reduce_add_sync(0xFFFFFFFFu, cg);
    int rem = TOPK - cg;

    unsigned lmask = (1u << lane) - 1u;
    unsigned long long selmask = 0ull;
    unsigned kmin_in = 0xFFFFFFFFu;
    unsigned kmax_out = 0u;
#pragma unroll 1
    for (int j = 0; j < 64; j++) {
        unsigned k = key[j];
        bool eq = (k == T);
        unsigned em = __ballot_sync(0xFFFFFFFFu, eq);
        bool pick = eq && ((int)__popc(em & lmask) < rem);
        bool sel  = (k > T) || pick;
        if (sel) { selmask |= (1ull << j); if (k < kmin_in) kmin_in = k; }
        else     { if (k > kmax_out) kmax_out = k; }
        rem -= __popc(em);
        if (rem < 0) rem = 0;
    }
    kmin_in  = __reduce_min_sync(0xFFFFFFFFu, kmin_in);
    kmax_out = __reduce_max_sync(0xFFFFFFFFu, kmax_out);

    float vin  = key_decode(kmin_in);
    float vout = key_decode(kmax_out);

    if (vin - vout < AMBIG_W) {
        float wlo = vout - AMBIG_W;
        float whi = vin + AMBIG_W;
        int ncand = 0;
#pragma unroll 1
        for (int j = 0; j < 64; j++) {
            float v = key_decode(key[j]);
            bool isc = (v >= wlo) && (v <= whi);
            unsigned bal = __ballot_sync(0xFFFFFFFFu, isc);
            if (isc) {
                int pos = ncand + __popc(bal & lmask);
                if (pos < MAXCAND) {
                    s_cidx[warp][pos] = j * 32 + lane;
                    s_csel[warp][pos] = (int)((selmask >> j) & 1ull);
                }
            }
            ncand += __popc(bal);
        }
        if (ncand > MAXCAND) ncand = MAXCAND;
        __syncwarp();

        const float* xr = x + (size_t)row * DIN;
        for (int c = 0; c < ncand; c++) {
            const float* wr = Wenc + (size_t)s_cidx[warp][c] * DIN;
            double s = 0.0;
#pragma unroll
            for (int t = 0; t < DIN / 32; t++) {
                int kk = lane + t * 32;
                s += (double)xr[kk] * (double)wr[kk];
            }
#pragma unroll
            for (int off = 16; off > 0; off >>= 1)
                s += __shfl_down_sync(0xFFFFFFFFu, s, off);
            if (lane == 0) s_cval[warp][c] = s;
            __syncwarp();
        }

        if (lane == 0) {
            int nkeep = 0;
            for (int c = 0; c < ncand; c++) nkeep += s_csel[warp][c];
            unsigned chosen = 0;
            for (int s = 0; s < nkeep; s++) {
                int best = -1;
                for (int c = 0; c < ncand; c++) {
                    if (chosen & (1u << c)) continue;
                    if (best < 0 ||
                        s_cval[warp][c] > s_cval[warp][best] ||
                        (s_cval[warp][c] == s_cval[warp][best] &&
                         s_cidx[warp][c] < s_cidx[warp][best]))
                        best = c;
                }
                chosen |= (1u << best);
            }
            s_chosen[warp] = chosen;
        }
        __syncwarp();
        unsigned chosen = s_chosen[warp];

        for (int c = 0; c < ncand; c++) {
            int fi = s_cidx[warp][c];
            if ((fi & 31) == lane) {
                int j = fi >> 5;
                if (chosen & (1u << c)) selmask |=  (1ull << j);
                else                    selmask &= ~(1ull << j);
            }
        }
        __syncwarp();
    }

    float* orow = hsp + (size_t)row * DHID;
    int nsel = 0;
#pragma unroll 1
    for (int j = 0; j < 64; j++) {
        bool sel = (selmask >> j) & 1ull;
        unsigned k = key[j];
        float v = (k > 0x80000000u) ? __uint_as_float(k ^ 0x80000000u) : 0.0f;
        orow[j * 32 + lane] = sel ? v : 0.0f;

        unsigned sm2 = __ballot_sync(0xFFFFFFFFu, sel);
        if (sel) {
            int slot = nsel + __popc(sm2 & lmask);
            g_tidx[(size_t)row * TOPK + slot] = j * 32 + lane;
            g_tval[(size_t)row * TOPK + slot] = v;
        }
        nsel += __popc(sm2);
    }
}

// ============================================================
// Sparse decoder: recon[row,:] = b_dec + sum_k val_k * Wt[idx_k,:]
// ============================================================
__global__ __launch_bounds__(192)
void decode_kernel(const float* __restrict__ bdec, float* __restrict__ recon)
{
    int row = blockIdx.x;
    int t = threadIdx.x;
    __shared__ float sval[TOPK];
    __shared__ int   sidx[TOPK];
    if (t < TOPK) {
        sval[t] = g_tval[(size_t)row * TOPK + t];
        sidx[t] = g_tidx[(size_t)row * TOPK + t];
    }
    __syncthreads();

    float4 acc = *(const float4*)&bdec[t * 4];
#pragma unroll 8
    for (int k = 0; k < TOPK; k++) {
        float v = sval[k];
        float4 w = *(const float4*)&g_Wt[(size_t)sidx[k] * DIN + t * 4];
        acc.x += v * w.x; acc.y += v * w.y; acc.z += v * w.z; acc.w += v * w.w;
    }
    *(float4*)&recon[(size_t)row * DIN + t * 4] = acc;
}

// ============================================================
extern "C" void kernel_launch(void* const* d_in, const int* in_sizes, int n_in,
                              void* d_out, int out_size)
{
    const float* x     = (const float*)d_in[0];
    const float* W_enc = (const float*)d_in[1];
    const float* b_enc = (const float*)d_in[2];
    const float* W_dec = (const float*)d_in[3];
    const float* b_dec = (const float*)d_in[4];

    float* out   = (float*)d_out;
    float* recon = out;                                 // [B, 768]
    float* hsp   = out + (size_t)BATCH * DIN;           // [B, 2048]
    float* hpre  = hsp + (size_t)BATCH * DHID;          // [B, 2048]

    __nv_bfloat16 *ah, *al, *bh, *bl;
    cudaGetSymbolAddress((void**)&ah, g_Ah);
    cudaGetSymbolAddress((void**)&al, g_Al);
    cudaGetSymbolAddress((void**)&bh, g_Bh);
    cudaGetSymbolAddress((void**)&bl, g_Bl);

    cudaFuncSetAttribute(gemm_bf16x3, cudaFuncAttributeMaxDynamicSharedMemorySize,
                         (int)GEMM_SMEM);

    split_kernel<<<(BATCH * DIN / 2) / 256, 256>>>(x, ah, al);
    split_kernel<<<(DHID * DIN / 2) / 256, 256>>>(W_enc, bh, bl);
    transpose_kernel<<<dim3(DHID / 32, DIN / 32), dim3(32, 8)>>>(W_dec);
    gemm_bf16x3<<<dim3(DHID / 256, BATCH / 128), 512, GEMM_SMEM>>>(b_enc, hpre);
    topk_kernel<<<BATCH / 8, 256>>>(hpre, hsp, x, W_enc);
    decode_kernel<<<BATCH, 192>>>(b_dec, recon);
}

// round 7
// speedup vs baseline: 2.9115x; 1.1019x over previous
#include <cuda_runtime.h>
#include <cuda_bf16.h>
#include <mma.h>
#include <cstdint>

using namespace nvcuda;

#define BATCH 32768
#define DIN   768
#define DHID  2048
#define TOPK  32

// -------- scratch (no cudaMalloc allowed) --------
__device__ __align__(16) float g_Wt[(size_t)DHID * DIN];   // W_dec^T [2048][768]
__device__ int   g_tidx[(size_t)BATCH * TOPK];
__device__ float g_tval[(size_t)BATCH * TOPK];
__device__ __align__(16) __nv_bfloat16 g_Ah[(size_t)BATCH * DIN];
__device__ __align__(16) __nv_bfloat16 g_Al[(size_t)BATCH * DIN];
__device__ __align__(16) __nv_bfloat16 g_Bh[(size_t)DHID * DIN];
__device__ __align__(16) __nv_bfloat16 g_Bl[(size_t)DHID * DIN];

// ============================================================
// f32 -> (hi, lo) bf16 split
// ============================================================
__global__ __launch_bounds__(256)
void split_kernel(const float* __restrict__ src,
                  __nv_bfloat16* __restrict__ hi,
                  __nv_bfloat16* __restrict__ lo)
{
    int i = blockIdx.x * 256 + threadIdx.x;
    float2 v = ((const float2*)src)[i];
    __nv_bfloat16 h0 = __float2bfloat16(v.x);
    __nv_bfloat16 h1 = __float2bfloat16(v.y);
    __nv_bfloat16 l0 = __float2bfloat16(v.x - __bfloat162float(h0));
    __nv_bfloat16 l1 = __float2bfloat16(v.y - __bfloat162float(h1));
    ((__nv_bfloat162*)hi)[i] = __halves2bfloat162(h0, h1);
    ((__nv_bfloat162*)lo)[i] = __halves2bfloat162(l0, l1);
}

// ============================================================
// W_dec [768][2048] -> g_Wt [2048][768]
// ============================================================
__global__ void transpose_kernel(const float* __restrict__ W)
{
    __shared__ float tile[32][33];
    int bx = blockIdx.x * 32, by = blockIdx.y * 32;
    int tx = threadIdx.x, ty = threadIdx.y;
#pragma unroll
    for (int i = 0; i < 32; i += 8)
        tile[ty + i][tx] = W[(size_t)(by + ty + i) * DHID + bx + tx];
    __syncthreads();
#pragma unroll
    for (int i = 0; i < 32; i += 8)
        g_Wt[(size_t)(bx + ty + i) * DIN + by + tx] = tile[tx][ty + i];
}

// ============================================================
// Encoder GEMM, bf16 3-split, cp.async 2-stage, 2 CTAs/SM.
//   C[m,n] = sum_k A[m,k]*B[n,k] + bias[n]
// Block 128x128, BK=32, 256 thr (8 warps 4x2), warp tile 32x64.
// Stage: Ah|Al|Bh|Bl, each 128 x 40 halves. 2 stages = 81920 B.
// ============================================================
#define BK     32
#define HS     40                       // halves per row (32 + 8 pad)
#define PART   (128 * HS)               // halves per matrix part
#define STG_H  (4 * PART)               // halves per stage
#define NKT    (DIN / BK)               // 24
#define GEMM_SMEM (2 * STG_H * sizeof(__nv_bfloat16))   // 81920 B

__device__ __forceinline__ void cp16(__nv_bfloat16* dst, const __nv_bfloat16* src)
{
    unsigned d = (unsigned)__cvta_generic_to_shared(dst);
    asm volatile("cp.async.cg.shared.global [%0], [%1], 16;\n" :: "r"(d), "l"(src));
}

__global__ __launch_bounds__(256, 2)
void gemm_bf16x3(const float* __restrict__ bias, float* __restrict__ C)
{
    extern __shared__ __nv_bfloat16 smh[];   // 2 stages

    int tid  = threadIdx.x;
    int warp = tid >> 5;
    int wm   = warp & 3;
    int wn   = warp >> 2;
    int m0 = blockIdx.y * 128;
    int n0 = blockIdx.x * 128;

    using FragA = wmma::fragment<wmma::matrix_a, 16, 16, 16, __nv_bfloat16, wmma::row_major>;
    using FragB = wmma::fragment<wmma::matrix_b, 16, 16, 16, __nv_bfloat16, wmma::col_major>;
    using FragC = wmma::fragment<wmma::accumulator, 16, 16, 16, float>;

    // ---- bias init via smem f32 broadcast tile (reuses stage region) ----
    float* bsm = (float*)smh;
    for (int i = tid; i < 16 * 128; i += 256)
        bsm[i] = bias[n0 + (i & 127)];
    __syncthreads();

    FragC acc[2][4];
#pragma unroll
    for (int i = 0; i < 2; i++)
#pragma unroll
        for (int j = 0; j < 4; j++)
            wmma::load_matrix_sync(acc[i][j], &bsm[wn * 64 + j * 16], 128, wmma::mem_row_major);
    __syncthreads();

    auto load_tile = [&](int buf, int kt) {
        __nv_bfloat16* s = smh + buf * STG_H;
        int k0 = kt * BK;
#pragma unroll
        for (int p = 0; p < 2; p++) {
            int f  = tid + p * 256;      // 0..511
            int r  = f >> 2;             // 0..127
            int ch = (f & 3) * 8;        // halves offset 0,8,16,24
            size_t ga = (size_t)(m0 + r) * DIN + k0 + ch;
            size_t gb = (size_t)(n0 + r) * DIN + k0 + ch;
            cp16(&s[0 * PART + r * HS + ch], &g_Ah[ga]);
            cp16(&s[1 * PART + r * HS + ch], &g_Al[ga]);
            cp16(&s[2 * PART + r * HS + ch], &g_Bh[gb]);
            cp16(&s[3 * PART + r * HS + ch], &g_Bl[gb]);
        }
        asm volatile("cp.async.commit_group;\n" ::);
    };

    load_tile(0, 0);

    for (int t = 0; t < NKT; t++) {
        if (t + 1 < NKT) load_tile((t + 1) & 1, t + 1);
        else             asm volatile("cp.async.commit_group;\n" ::);

        asm volatile("cp.async.wait_group 1;\n" ::);
        __syncthreads();

        __nv_bfloat16* s  = smh + (t & 1) * STG_H;
        __nv_bfloat16* Ah = s;
        __nv_bfloat16* Al = s + PART;
        __nv_bfloat16* Bh = s + 2 * PART;
        __nv_bfloat16* Bl = s + 3 * PART;

#pragma unroll
        for (int ks = 0; ks < BK; ks += 16) {
            FragA ah[2], al[2];
#pragma unroll
            for (int i = 0; i < 2; i++) {
                wmma::load_matrix_sync(ah[i], &Ah[(wm * 32 + i * 16) * HS + ks], HS);
                wmma::load_matrix_sync(al[i], &Al[(wm * 32 + i * 16) * HS + ks], HS);
            }
#pragma unroll
            for (int j = 0; j < 4; j++) {
                FragB bh, bl;
                wmma::load_matrix_sync(bh, &Bh[(wn * 64 + j * 16) * HS + ks], HS);
                wmma::load_matrix_sync(bl, &Bl[(wn * 64 + j * 16) * HS + ks], HS);
#pragma unroll
                for (int i = 0; i < 2; i++) {
                    wmma::mma_sync(acc[i][j], ah[i], bl, acc[i][j]);
                    wmma::mma_sync(acc[i][j], al[i], bh, acc[i][j]);
                    wmma::mma_sync(acc[i][j], ah[i], bh, acc[i][j]);
                }
            }
        }
        __syncthreads();
    }

#pragma unroll
    for (int i = 0; i < 2; i++)
#pragma unroll
        for (int j = 0; j < 4; j++) {
            float* cp = &C[(size_t)(m0 + wm * 32 + i * 16) * DHID + n0 + wn * 64 + j * 16];
            wmma::store_matrix_sync(cp, acc[i][j], DHID, wmma::mem_row_major);
        }
}

// ============================================================
// Top-K with exact fp64 re-ranking of the ambiguous boundary.
// ============================================================
#define AMBIG_W 1e-4f
#define MAXCAND 16

__device__ __forceinline__ float key_decode(unsigned k)
{
    return (k >= 0x80000000u) ? __uint_as_float(k ^ 0x80000000u)
                              : __uint_as_float(~k);
}

__global__ __launch_bounds__(256)
void topk_kernel(const float* __restrict__ hpre, float* __restrict__ hsp,
                 const float* __restrict__ x, const float* __restrict__ Wenc)
{
    int lane = threadIdx.x & 31;
    int warp = threadIdx.x >> 5;
    int row  = blockIdx.x * 8 + warp;
    const float* p = hpre + (size_t)row * DHID;

    __shared__ int    s_cidx[8][MAXCAND];
    __shared__ double s_cval[8][MAXCAND];
    __shared__ int    s_csel[8][MAXCAND];
    __shared__ unsigned s_chosen[8];

    unsigned key[64];
#pragma unroll
    for (int j = 0; j < 64; j++) {
        unsigned u = __float_as_uint(p[j * 32 + lane]);
        key[j] = (u & 0x80000000u) ? ~u : (u | 0x80000000u);
    }

    unsigned lo = 0u, hi = 0xFFFFFFFFu;
#pragma unroll 1
    for (int it = 0; it < 32; ++it) {
        if (lo >= hi) break;
        unsigned span = hi - lo;
        unsigned mid = lo + (span >> 1) + (span & 1u);
        int c = 0;
#pragma unroll
        for (int j = 0; j < 64; j++) c += (key[j] >= mid) ? 1 : 0;
        c = __reduce_add_sync(0xFFFFFFFFu, c);
        if (c >= TOPK) lo = mid; else hi = mid - 1;
    }
    unsigned T = lo;

    int cg = 0;
#pragma unroll
    for (int j = 0; j < 64; j++) cg += (key[j] > T) ? 1 : 0;
    cg = __reduce_add_sync(0xFFFFFFFFu, cg);
    int rem = TOPK - cg;

    unsigned lmask = (1u << lane) - 1u;
    unsigned long long selmask = 0ull;
    unsigned kmin_in = 0xFFFFFFFFu;
    unsigned kmax_out = 0u;
#pragma unroll 1
    for (int j = 0; j < 64; j++) {
        unsigned k = key[j];
        bool eq = (k == T);
        unsigned em = __ballot_sync(0xFFFFFFFFu, eq);
        bool pick = eq && ((int)__popc(em & lmask) < rem);
        bool sel  = (k > T) || pick;
        if (sel) { selmask |= (1ull << j); if (k < kmin_in) kmin_in = k; }
        else     { if (k > kmax_out) kmax_out = k; }
        rem -= __popc(em);
        if (rem < 0) rem = 0;
    }
    kmin_in  = __reduce_min_sync(0xFFFFFFFFu, kmin_in);
    kmax_out = __reduce_max_sync(0xFFFFFFFFu, kmax_out);

    float vin  = key_decode(kmin_in);
    float vout = key_decode(kmax_out);

    if (vin - vout < AMBIG_W) {
        float wlo = vout - AMBIG_W;
        float whi = vin + AMBIG_W;
        int ncand = 0;
#pragma unroll 1
        for (int j = 0; j < 64; j++) {
            float v = key_decode(key[j]);
            bool isc = (v >= wlo) && (v <= whi);
            unsigned bal = __ballot_sync(0xFFFFFFFFu, isc);
            if (isc) {
                int pos = ncand + __popc(bal & lmask);
                if (pos < MAXCAND) {
                    s_cidx[warp][pos] = j * 32 + lane;
                    s_csel[warp][pos] = (int)((selmask >> j) & 1ull);
                }
            }
            ncand += __popc(bal);
        }
        if (ncand > MAXCAND) ncand = MAXCAND;
        __syncwarp();

        const float* xr = x + (size_t)row * DIN;
        for (int c = 0; c < ncand; c++) {
            const float* wr = Wenc + (size_t)s_cidx[warp][c] * DIN;
            double s = 0.0;
#pragma unroll
            for (int t = 0; t < DIN / 32; t++) {
                int kk = lane + t * 32;
                s += (double)xr[kk] * (double)wr[kk];
            }
#pragma unroll
            for (int off = 16; off > 0; off >>= 1)
                s += __shfl_down_sync(0xFFFFFFFFu, s, off);
            if (lane == 0) s_cval[warp][c] = s;
            __syncwarp();
        }

        if (lane == 0) {
            int nkeep = 0;
            for (int c = 0; c < ncand; c++) nkeep += s_csel[warp][c];
            unsigned chosen = 0;
            for (int s = 0; s < nkeep; s++) {
                int best = -1;
                for (int c = 0; c < ncand; c++) {
                    if (chosen & (1u << c)) continue;
                    if (best < 0 ||
                        s_cval[warp][c] > s_cval[warp][best] ||
                        (s_cval[warp][c] == s_cval[warp][best] &&
                         s_cidx[warp][c] < s_cidx[warp][best]))
                        best = c;
                }
                chosen |= (1u << best);
            }
            s_chosen[warp] = chosen;
        }
        __syncwarp();
        unsigned chosen = s_chosen[warp];

        for (int c = 0; c < ncand; c++) {
            int fi = s_cidx[warp][c];
            if ((fi & 31) == lane) {
                int j = fi >> 5;
                if (chosen & (1u << c)) selmask |=  (1ull << j);
                else                    selmask &= ~(1ull << j);
            }
        }
        __syncwarp();
    }

    float* orow = hsp + (size_t)row * DHID;
    int nsel = 0;
#pragma unroll 1
    for (int j = 0; j < 64; j++) {
        bool sel = (selmask >> j) & 1ull;
        unsigned k = key[j];
        float v = (k > 0x80000000u) ? __uint_as_float(k ^ 0x80000000u) : 0.0f;
        orow[j * 32 + lane] = sel ? v : 0.0f;

        unsigned sm2 = __ballot_sync(0xFFFFFFFFu, sel);
        if (sel) {
            int slot = nsel + __popc(sm2 & lmask);
            g_tidx[(size_t)row * TOPK + slot] = j * 32 + lane;
            g_tval[(size_t)row * TOPK + slot] = v;
        }
        nsel += __popc(sm2);
    }
}

// ============================================================
// Sparse decoder: recon[row,:] = b_dec + sum_k val_k * Wt[idx_k,:]
// ============================================================
__global__ __launch_bounds__(192)
void decode_kernel(const float* __restrict__ bdec, float* __restrict__ recon)
{
    int row = blockIdx.x;
    int t = threadIdx.x;
    __shared__ float sval[TOPK];
    __shared__ int   sidx[TOPK];
    if (t < TOPK) {
        sval[t] = g_tval[(size_t)row * TOPK + t];
        sidx[t] = g_tidx[(size_t)row * TOPK + t];
    }
    __syncthreads();

    float4 acc = *(const float4*)&bdec[t * 4];
#pragma unroll 8
    for (int k = 0; k < TOPK; k++) {
        float v = sval[k];
        float4 w = *(const float4*)&g_Wt[(size_t)sidx[k] * DIN + t * 4];
        acc.x += v * w.x; acc.y += v * w.y; acc.z += v * w.z; acc.w += v * w.w;
    }
    *(float4*)&recon[(size_t)row * DIN + t * 4] = acc;
}

// ============================================================
extern "C" void kernel_launch(void* const* d_in, const int* in_sizes, int n_in,
                              void* d_out, int out_size)
{
    const float* x     = (const float*)d_in[0];
    const float* W_enc = (const float*)d_in[1];
    const float* b_enc = (const float*)d_in[2];
    const float* W_dec = (const float*)d_in[3];
    const float* b_dec = (const float*)d_in[4];

    float* out   = (float*)d_out;
    float* recon = out;                                 // [B, 768]
    float* hsp   = out + (size_t)BATCH * DIN;           // [B, 2048]
    float* hpre  = hsp + (size_t)BATCH * DHID;          // [B, 2048]

    __nv_bfloat16 *ah, *al, *bh, *bl;
    cudaGetSymbolAddress((void**)&ah, g_Ah);
    cudaGetSymbolAddress((void**)&al, g_Al);
    cudaGetSymbolAddress((void**)&bh, g_Bh);
    cudaGetSymbolAddress((void**)&bl, g_Bl);

    cudaFuncSetAttribute(gemm_bf16x3, cudaFuncAttributeMaxDynamicSharedMemorySize,
                         (int)GEMM_SMEM);

    split_kernel<<<(BATCH * DIN / 2) / 256, 256>>>(x, ah, al);
    split_kernel<<<(DHID * DIN / 2) / 256, 256>>>(W_enc, bh, bl);
    transpose_kernel<<<dim3(DHID / 32, DIN / 32), dim3(32, 8)>>>(W_dec);
    gemm_bf16x3<<<dim3(DHID / 128, BATCH / 128), 256, GEMM_SMEM>>>(b_enc, hpre);
    topk_kernel<<<BATCH / 8, 256>>>(hpre, hsp, x, W_enc);
    decode_kernel<<<BATCH, 192>>>(b_dec, recon);
}

// round 8
// speedup vs baseline: 3.0465x; 1.0464x over previous
#include <cuda_runtime.h>
#include <cuda_bf16.h>
#include <mma.h>
#include <cstdint>

using namespace nvcuda;

#define BATCH 32768
#define DIN   768
#define DHID  2048
#define TOPK  32

// -------- scratch (no cudaMalloc allowed) --------
__device__ __align__(16) float g_Wt[(size_t)DHID * DIN];   // W_dec^T [2048][768]
__device__ int   g_tidx[(size_t)BATCH * TOPK];
__device__ float g_tval[(size_t)BATCH * TOPK];
__device__ __align__(16) __nv_bfloat16 g_Ah[(size_t)BATCH * DIN];
__device__ __align__(16) __nv_bfloat16 g_Al[(size_t)BATCH * DIN];
__device__ __align__(16) __nv_bfloat16 g_Bh[(size_t)DHID * DIN];
__device__ __align__(16) __nv_bfloat16 g_Bl[(size_t)DHID * DIN];

// ============================================================
// f32 -> (hi, lo) bf16 split
// ============================================================
__global__ __launch_bounds__(256)
void split_kernel(const float* __restrict__ src,
                  __nv_bfloat16* __restrict__ hi,
                  __nv_bfloat16* __restrict__ lo)
{
    int i = blockIdx.x * 256 + threadIdx.x;
    float2 v = ((const float2*)src)[i];
    __nv_bfloat16 h0 = __float2bfloat16(v.x);
    __nv_bfloat16 h1 = __float2bfloat16(v.y);
    __nv_bfloat16 l0 = __float2bfloat16(v.x - __bfloat162float(h0));
    __nv_bfloat16 l1 = __float2bfloat16(v.y - __bfloat162float(h1));
    ((__nv_bfloat162*)hi)[i] = __halves2bfloat162(h0, h1);
    ((__nv_bfloat162*)lo)[i] = __halves2bfloat162(l0, l1);
}

// ============================================================
// W_dec [768][2048] -> g_Wt [2048][768]
// ============================================================
__global__ void transpose_kernel(const float* __restrict__ W)
{
    __shared__ float tile[32][33];
    int bx = blockIdx.x * 32, by = blockIdx.y * 32;
    int tx = threadIdx.x, ty = threadIdx.y;
#pragma unroll
    for (int i = 0; i < 32; i += 8)
        tile[ty + i][tx] = W[(size_t)(by + ty + i) * DHID + bx + tx];
    __syncthreads();
#pragma unroll
    for (int i = 0; i < 32; i += 8)
        g_Wt[(size_t)(bx + ty + i) * DIN + by + tx] = tile[tx][ty + i];
}

// ============================================================
// Encoder GEMM, bf16 3-split, cp.async 2-stage, 2 CTAs/SM.
// Term-sweep ordering: all 8 (i,j) fragments per term -> RAW
// revisit distance 8 independent HMMAs.
// ============================================================
#define BK     32
#define HS     40                       // halves per row (32 + 8 pad)
#define PART   (128 * HS)               // halves per matrix part
#define STG_H  (4 * PART)               // halves per stage
#define NKT    (DIN / BK)               // 24
#define GEMM_SMEM (2 * STG_H * sizeof(__nv_bfloat16))   // 81920 B

__device__ __forceinline__ void cp16(__nv_bfloat16* dst, const __nv_bfloat16* src)
{
    unsigned d = (unsigned)__cvta_generic_to_shared(dst);
    asm volatile("cp.async.cg.shared.global [%0], [%1], 16;\n" :: "r"(d), "l"(src));
}

__global__ __launch_bounds__(256, 2)
void gemm_bf16x3(const float* __restrict__ bias, float* __restrict__ C)
{
    extern __shared__ __nv_bfloat16 smh[];   // 2 stages

    int tid  = threadIdx.x;
    int warp = tid >> 5;
    int wm   = warp & 3;
    int wn   = warp >> 2;
    int m0 = blockIdx.y * 128;
    int n0 = blockIdx.x * 128;

    using FragA = wmma::fragment<wmma::matrix_a, 16, 16, 16, __nv_bfloat16, wmma::row_major>;
    using FragB = wmma::fragment<wmma::matrix_b, 16, 16, 16, __nv_bfloat16, wmma::col_major>;
    using FragC = wmma::fragment<wmma::accumulator, 16, 16, 16, float>;

    // ---- bias init via smem f32 broadcast tile (reuses stage region) ----
    float* bsm = (float*)smh;
    for (int i = tid; i < 16 * 128; i += 256)
        bsm[i] = bias[n0 + (i & 127)];
    __syncthreads();

    FragC acc[2][4];
#pragma unroll
    for (int i = 0; i < 2; i++)
#pragma unroll
        for (int j = 0; j < 4; j++)
            wmma::load_matrix_sync(acc[i][j], &bsm[wn * 64 + j * 16], 128, wmma::mem_row_major);
    __syncthreads();

    auto load_tile = [&](int buf, int kt) {
        __nv_bfloat16* s = smh + buf * STG_H;
        int k0 = kt * BK;
#pragma unroll
        for (int p = 0; p < 2; p++) {
            int f  = tid + p * 256;      // 0..511
            int r  = f >> 2;             // 0..127
            int ch = (f & 3) * 8;        // halves offset 0,8,16,24
            size_t ga = (size_t)(m0 + r) * DIN + k0 + ch;
            size_t gb = (size_t)(n0 + r) * DIN + k0 + ch;
            cp16(&s[0 * PART + r * HS + ch], &g_Ah[ga]);
            cp16(&s[1 * PART + r * HS + ch], &g_Al[ga]);
            cp16(&s[2 * PART + r * HS + ch], &g_Bh[gb]);
            cp16(&s[3 * PART + r * HS + ch], &g_Bl[gb]);
        }
        asm volatile("cp.async.commit_group;\n" ::);
    };

    load_tile(0, 0);

    for (int t = 0; t < NKT; t++) {
        if (t + 1 < NKT) load_tile((t + 1) & 1, t + 1);
        else             asm volatile("cp.async.commit_group;\n" ::);

        asm volatile("cp.async.wait_group 1;\n" ::);
        __syncthreads();

        __nv_bfloat16* s  = smh + (t & 1) * STG_H;
        __nv_bfloat16* Ah = s;
        __nv_bfloat16* Al = s + PART;
        __nv_bfloat16* Bh = s + 2 * PART;
        __nv_bfloat16* Bl = s + 3 * PART;

#pragma unroll
        for (int ks = 0; ks < BK; ks += 16) {
            FragA ah[2], al[2];
            FragB bh[4];
#pragma unroll
            for (int i = 0; i < 2; i++) {
                wmma::load_matrix_sync(ah[i], &Ah[(wm * 32 + i * 16) * HS + ks], HS);
                wmma::load_matrix_sync(al[i], &Al[(wm * 32 + i * 16) * HS + ks], HS);
            }
#pragma unroll
            for (int j = 0; j < 4; j++)
                wmma::load_matrix_sync(bh[j], &Bh[(wn * 64 + j * 16) * HS + ks], HS);

            // sweep 1: ah x bh  (8 independent HMMA streams)
#pragma unroll
            for (int j = 0; j < 4; j++)
#pragma unroll
                for (int i = 0; i < 2; i++)
                    wmma::mma_sync(acc[i][j], ah[i], bh[j], acc[i][j]);

            // sweep 2: ah x bl  (bl loaded just-in-time, transient)
#pragma unroll
            for (int j = 0; j < 4; j++) {
                FragB bl;
                wmma::load_matrix_sync(bl, &Bl[(wn * 64 + j * 16) * HS + ks], HS);
#pragma unroll
                for (int i = 0; i < 2; i++)
                    wmma::mma_sync(acc[i][j], ah[i], bl, acc[i][j]);
            }

            // sweep 3: al x bh
#pragma unroll
            for (int j = 0; j < 4; j++)
#pragma unroll
                for (int i = 0; i < 2; i++)
                    wmma::mma_sync(acc[i][j], al[i], bh[j], acc[i][j]);
        }
        __syncthreads();
    }

#pragma unroll
    for (int i = 0; i < 2; i++)
#pragma unroll
        for (int j = 0; j < 4; j++) {
            float* cp = &C[(size_t)(m0 + wm * 32 + i * 16) * DHID + n0 + wn * 64 + j * 16];
            wmma::store_matrix_sync(cp, acc[i][j], DHID, wmma::mem_row_major);
        }
}

// ============================================================
// Top-K with exact fp64 re-ranking of the ambiguous boundary.
// Binary search bounded by [min-lane-max, max-lane-max].
// ============================================================
#define AMBIG_W 1e-4f
#define MAXCAND 16

__device__ __forceinline__ float key_decode(unsigned k)
{
    return (k >= 0x80000000u) ? __uint_as_float(k ^ 0x80000000u)
                              : __uint_as_float(~k);
}

__global__ __launch_bounds__(256)
void topk_kernel(const float* __restrict__ hpre, float* __restrict__ hsp,
                 const float* __restrict__ x, const float* __restrict__ Wenc)
{
    int lane = threadIdx.x & 31;
    int warp = threadIdx.x >> 5;
    int row  = blockIdx.x * 8 + warp;
    const float* p = hpre + (size_t)row * DHID;

    __shared__ int    s_cidx[8][MAXCAND];
    __shared__ double s_cval[8][MAXCAND];
    __shared__ int    s_csel[8][MAXCAND];
    __shared__ unsigned s_chosen[8];

    unsigned key[64];
#pragma unroll
    for (int j = 0; j < 64; j++) {
        unsigned u = __float_as_uint(p[j * 32 + lane]);
        key[j] = (u & 0x80000000u) ? ~u : (u | 0x80000000u);
    }

    // per-lane max -> provable search bounds: m <= T* <= M
    unsigned lmax = 0u;
#pragma unroll
    for (int j = 0; j < 64; j++) lmax = (key[j] > lmax) ? key[j] : lmax;
    unsigned lo = __reduce_min_sync(0xFFFFFFFFu, lmax);
    unsigned hi = __reduce_max_sync(0xFFFFFFFFu, lmax);

#pragma unroll 1
    for (int it = 0; it < 32; ++it) {
        if (lo >= hi) break;
        unsigned span = hi - lo;
        unsigned mid = lo + (span >> 1) + (span & 1u);
        int c = 0;
#pragma unroll
        for (int j = 0; j < 64; j++) c += (key[j] >= mid) ? 1 : 0;
        c = __reduce_add_sync(0xFFFFFFFFu, c);
        if (c >= TOPK) lo = mid; else hi = mid - 1;
    }
    unsigned T = lo;

    int cg = 0;
#pragma unroll
    for (int j = 0; j < 64; j++) cg += (key[j] > T) ? 1 : 0;
    cg = __reduce_add_sync(0xFFFFFFFFu, cg);
    int rem = TOPK - cg;

    unsigned lmask = (1u << lane) - 1u;
    unsigned long long selmask = 0ull;
    unsigned kmin_in = 0xFFFFFFFFu;
    unsigned kmax_out = 0u;
#pragma unroll 1
    for (int j = 0; j < 64; j++) {
        unsigned k = key[j];
        bool eq = (k == T);
        unsigned em = __ballot_sync(0xFFFFFFFFu, eq);
        bool pick = eq && ((int)__popc(em & lmask) < rem);
        bool sel  = (k > T) || pick;
        if (sel) { selmask |= (1ull << j); if (k < kmin_in) kmin_in = k; }
        else     { if (k > kmax_out) kmax_out = k; }
        rem -= __popc(em);
        if (rem < 0) rem = 0;
    }
    kmin_in  = __reduce_min_sync(0xFFFFFFFFu, kmin_in);
    kmax_out = __reduce_max_sync(0xFFFFFFFFu, kmax_out);

    float vin  = key_decode(kmin_in);
    float vout = key_decode(kmax_out);

    if (vin - vout < AMBIG_W) {
        float wlo = vout - AMBIG_W;
        float whi = vin + AMBIG_W;
        int ncand = 0;
#pragma unroll 1
        for (int j = 0; j < 64; j++) {
            float v = key_decode(key[j]);
            bool isc = (v >= wlo) && (v <= whi);
            unsigned bal = __ballot_sync(0xFFFFFFFFu, isc);
            if (isc) {
                int pos = ncand + __popc(bal & lmask);
                if (pos < MAXCAND) {
                    s_cidx[warp][pos] = j * 32 + lane;
                    s_csel[warp][pos] = (int)((selmask >> j) & 1ull);
                }
            }
            ncand += __popc(bal);
        }
        if (ncand > MAXCAND) ncand = MAXCAND;
        __syncwarp();

        const float* xr = x + (size_t)row * DIN;
        for (int c = 0; c < ncand; c++) {
            const float* wr = Wenc + (size_t)s_cidx[warp][c] * DIN;
            double s = 0.0;
#pragma unroll
            for (int t = 0; t < DIN / 32; t++) {
                int kk = lane + t * 32;
                s += (double)xr[kk] * (double)wr[kk];
            }
#pragma unroll
            for (int off = 16; off > 0; off >>= 1)
                s += __shfl_down_sync(0xFFFFFFFFu, s, off);
            if (lane == 0) s_cval[warp][c] = s;
            __syncwarp();
        }

        if (lane == 0) {
            int nkeep = 0;
            for (int c = 0; c < ncand; c++) nkeep += s_csel[warp][c];
            unsigned chosen = 0;
            for (int s = 0; s < nkeep; s++) {
                int best = -1;
                for (int c = 0; c < ncand; c++) {
                    if (chosen & (1u << c)) continue;
                    if (best < 0 ||
                        s_cval[warp][c] > s_cval[warp][best] ||
                        (s_cval[warp][c] == s_cval[warp][best] &&
                         s_cidx[warp][c] < s_cidx[warp][best]))
                        best = c;
                }
                chosen |= (1u << best);
            }
            s_chosen[warp] = chosen;
        }
        __syncwarp();
        unsigned chosen = s_chosen[warp];

        for (int c = 0; c < ncand; c++) {
            int fi = s_cidx[warp][c];
            if ((fi & 31) == lane) {
                int j = fi >> 5;
                if (chosen & (1u << c)) selmask |=  (1ull << j);
                else                    selmask &= ~(1ull << j);
            }
        }
        __syncwarp();
    }

    float* orow = hsp + (size_t)row * DHID;
    int nsel = 0;
#pragma unroll 1
    for (int j = 0; j < 64; j++) {
        bool sel = (selmask >> j) & 1ull;
        unsigned k = key[j];
        float v = (k > 0x80000000u) ? __uint_as_float(k ^ 0x80000000u) : 0.0f;
        orow[j * 32 + lane] = sel ? v : 0.0f;

        unsigned sm2 = __ballot_sync(0xFFFFFFFFu, sel);
        if (sel) {
            int slot = nsel + __popc(sm2 & lmask);
            g_tidx[(size_t)row * TOPK + slot] = j * 32 + lane;
            g_tval[(size_t)row * TOPK + slot] = v;
        }
        nsel += __popc(sm2);
    }
}

// ============================================================
// Sparse decoder: recon[row,:] = b_dec + sum_k val_k * Wt[idx_k,:]
// ============================================================
__global__ __launch_bounds__(192)
void decode_kernel(const float* __restrict__ bdec, float* __restrict__ recon)
{
    int row = blockIdx.x;
    int t = threadIdx.x;
    __shared__ float sval[TOPK];
    __shared__ int   sidx[TOPK];
    if (t < TOPK) {
        sval[t] = g_tval[(size_t)row * TOPK + t];
        sidx[t] = g_tidx[(size_t)row * TOPK + t];
    }
    __syncthreads();

    float4 acc = *(const float4*)&bdec[t * 4];
#pragma unroll 8
    for (int k = 0; k < TOPK; k++) {
        float v = sval[k];
        float4 w = *(const float4*)&g_Wt[(size_t)sidx[k] * DIN + t * 4];
        acc.x += v * w.x; acc.y += v * w.y; acc.z += v * w.z; acc.w += v * w.w;
    }
    *(float4*)&recon[(size_t)row * DIN + t * 4] = acc;
}

// ============================================================
extern "C" void kernel_launch(void* const* d_in, const int* in_sizes, int n_in,
                              void* d_out, int out_size)
{
    const float* x     = (const float*)d_in[0];
    const float* W_enc = (const float*)d_in[1];
    const float* b_enc = (const float*)d_in[2];
    const float* W_dec = (const float*)d_in[3];
    const float* b_dec = (const float*)d_in[4];

    float* out   = (float*)d_out;
    float* recon = out;                                 // [B, 768]
    float* hsp   = out + (size_t)BATCH * DIN;           // [B, 2048]
    float* hpre  = hsp + (size_t)BATCH * DHID;          // [B, 2048]

    __nv_bfloat16 *ah, *al, *bh, *bl;
    cudaGetSymbolAddress((void**)&ah, g_Ah);
    cudaGetSymbolAddress((void**)&al, g_Al);
    cudaGetSymbolAddress((void**)&bh, g_Bh);
    cudaGetSymbolAddress((void**)&bl, g_Bl);

    cudaFuncSetAttribute(gemm_bf16x3, cudaFuncAttributeMaxDynamicSharedMemorySize,
                         (int)GEMM_SMEM);

    split_kernel<<<(BATCH * DIN / 2) / 256, 256>>>(x, ah, al);
    split_kernel<<<(DHID * DIN / 2) / 256, 256>>>(W_enc, bh, bl);
    transpose_kernel<<<dim3(DHID / 32, DIN / 32), dim3(32, 8)>>>(W_dec);
    gemm_bf16x3<<<dim3(DHID / 128, BATCH / 128), 256, GEMM_SMEM>>>(b_enc, hpre);
    topk_kernel<<<BATCH / 8, 256>>>(hpre, hsp, x, W_enc);
    decode_kernel<<<BATCH, 192>>>(b_dec, recon);
}